// round 14
// baseline (speedup 1.0000x reference)
#include <cuda_runtime.h>
#include <math.h>
#include <stdint.h>

#define TOKENS 4096
#define SEQ    2048
#define EMB    1024
#define RANK   256
#define NH     16
#define NBH    32

// ---------------- scratch ----------------
__device__ float g_qlat [TOKENS * RANK];
__device__ float g_krlat[TOKENS * RANK];
__device__ float g_kv   [TOKENS * RANK];
__device__ float g_qr   [TOKENS * EMB];
__device__ float g_qn   [TOKENS * EMB];
__device__ float g_krf  [TOKENS * EMB];
__device__ float g_knf  [TOKENS * EMB];
__device__ float g_q    [(size_t)NBH * SEQ * 128];
__device__ float g_k    [(size_t)NBH * SEQ * 128];
__device__ float g_v    [(size_t)NBH * SEQ * 64];
__device__ float g_y    [TOKENS * EMB];
__device__ float g_rope [SEQ * 64];   // [s][0..31]=cos, [s][32..63]=sin

// ---------------- helpers ----------------
__device__ __forceinline__ uint32_t f2t(float x) {
    uint32_t r;
    asm("cvt.rna.tf32.f32 %0, %1;" : "=r"(r) : "f"(x));
    return r;
}
__device__ __forceinline__ float f2tf(float x) { return __uint_as_float(f2t(x)); }

__device__ __forceinline__ void mma8(float* d, const uint32_t* a, const uint32_t* b) {
    asm volatile(
        "mma.sync.aligned.m16n8k8.row.col.f32.tf32.tf32.f32 "
        "{%0,%1,%2,%3}, {%4,%5,%6,%7}, {%8,%9}, {%0,%1,%2,%3};"
        : "+f"(d[0]), "+f"(d[1]), "+f"(d[2]), "+f"(d[3])
        : "r"(a[0]), "r"(a[1]), "r"(a[2]), "r"(a[3]), "r"(b[0]), "r"(b[1]));
}

// ---------------- tf32 GEMM body: C = A(128 rows) * B(128 rows)^T ----------------
// BM=128, BN=128, BK=32, 256 threads (8 warps: 2M x 4N, warp tile 64x32).
// SPLIT: 3-pass hi/lo error compensation. PACKV: epilogue writes [bh][s][64] layout.
#define GSTR 36

template <int K, int N, bool SPLIT, bool PACKV>
__device__ __forceinline__ void gemm_body(const float* __restrict__ A,
                                          const float* __restrict__ B,
                                          float* __restrict__ C,
                                          int row0, int col0) {
    extern __shared__ float smg[];
    float* sAh = smg;
    float* sBh = sAh + 128 * GSTR;
    float* sAl = sBh + 128 * GSTR;           // only used if SPLIT
    float* sBl = sAl + 128 * GSTR;

    const int tid = threadIdx.x, lane = tid & 31, warp = tid >> 5;
    const int g = lane >> 2, t = lane & 3;
    const int wm = warp >> 2, wn = warp & 3;

    const float* Ab = A + (size_t)row0 * K;
    const float* Bb = B + (size_t)col0 * K;

    int rr[4], cc[4];
#pragma unroll
    for (int i = 0; i < 4; i++) { int idx = tid + i * 256; rr[i] = idx >> 3; cc[i] = (idx & 7) << 2; }

    float4 pa[4], pb[4];
#pragma unroll
    for (int i = 0; i < 4; i++) {
        pa[i] = *(const float4*)(Ab + (size_t)rr[i] * K + cc[i]);
        pb[i] = *(const float4*)(Bb + (size_t)rr[i] * K + cc[i]);
    }

    float acc[4][4][4] = {};

#pragma unroll 1
    for (int k0 = 0; k0 < K; k0 += 32) {
        __syncthreads();
#pragma unroll
        for (int i = 0; i < 4; i++) {
            float4 v = pa[i];
            float hx = f2tf(v.x), hy = f2tf(v.y), hz = f2tf(v.z), hw = f2tf(v.w);
            *(float4*)(sAh + rr[i] * GSTR + cc[i]) = make_float4(hx, hy, hz, hw);
            if (SPLIT)
                *(float4*)(sAl + rr[i] * GSTR + cc[i]) =
                    make_float4(f2tf(v.x - hx), f2tf(v.y - hy), f2tf(v.z - hz), f2tf(v.w - hw));
            v = pb[i];
            hx = f2tf(v.x); hy = f2tf(v.y); hz = f2tf(v.z); hw = f2tf(v.w);
            *(float4*)(sBh + rr[i] * GSTR + cc[i]) = make_float4(hx, hy, hz, hw);
            if (SPLIT)
                *(float4*)(sBl + rr[i] * GSTR + cc[i]) =
                    make_float4(f2tf(v.x - hx), f2tf(v.y - hy), f2tf(v.z - hz), f2tf(v.w - hw));
        }
        __syncthreads();
        if (k0 + 32 < K) {
#pragma unroll
            for (int i = 0; i < 4; i++) {
                pa[i] = *(const float4*)(Ab + (size_t)rr[i] * K + k0 + 32 + cc[i]);
                pb[i] = *(const float4*)(Bb + (size_t)rr[i] * K + k0 + 32 + cc[i]);
            }
        }
#pragma unroll
        for (int k8 = 0; k8 < 4; k8++) {
            const int kb = k8 * 8 + t;
            uint32_t ah[4][4], al[4][4], bh[4][2], bl[4][2];
#pragma unroll
            for (int mt = 0; mt < 4; mt++) {
                const float* p = sAh + (wm * 64 + mt * 16 + g) * GSTR + kb;
                ah[mt][0] = __float_as_uint(p[0]);
                ah[mt][1] = __float_as_uint(p[8 * GSTR]);
                ah[mt][2] = __float_as_uint(p[4]);
                ah[mt][3] = __float_as_uint(p[8 * GSTR + 4]);
                if (SPLIT) {
                    const float* q = sAl + (wm * 64 + mt * 16 + g) * GSTR + kb;
                    al[mt][0] = __float_as_uint(q[0]);
                    al[mt][1] = __float_as_uint(q[8 * GSTR]);
                    al[mt][2] = __float_as_uint(q[4]);
                    al[mt][3] = __float_as_uint(q[8 * GSTR + 4]);
                }
            }
#pragma unroll
            for (int nt = 0; nt < 4; nt++) {
                const float* p = sBh + (wn * 32 + nt * 8 + g) * GSTR + kb;
                bh[nt][0] = __float_as_uint(p[0]);
                bh[nt][1] = __float_as_uint(p[4]);
                if (SPLIT) {
                    const float* q = sBl + (wn * 32 + nt * 8 + g) * GSTR + kb;
                    bl[nt][0] = __float_as_uint(q[0]);
                    bl[nt][1] = __float_as_uint(q[4]);
                }
            }
#pragma unroll
            for (int mt = 0; mt < 4; mt++)
#pragma unroll
                for (int nt = 0; nt < 4; nt++) {
                    mma8(acc[mt][nt], ah[mt], bh[nt]);
                    if (SPLIT) {
                        mma8(acc[mt][nt], ah[mt], bl[nt]);
                        mma8(acc[mt][nt], al[mt], bh[nt]);
                    }
                }
        }
    }

#pragma unroll
    for (int mt = 0; mt < 4; mt++) {
        int r0 = row0 + wm * 64 + mt * 16 + g;
#pragma unroll
        for (int nt = 0; nt < 4; nt++) {
            int c = col0 + wn * 32 + nt * 8 + 2 * t;
            if (PACKV) {
                // pack [token][E] -> [b*16+h][s][64]
                int b0 = r0 >> 11, s0 = r0 & (SEQ - 1);
                int h = c >> 6, d = c & 63;
                float* P0 = C + (((size_t)(b0 * NH + h)) * SEQ + s0) * 64 + d;
                float* P1 = C + (((size_t)(b0 * NH + h)) * SEQ + s0 + 8) * 64 + d;
                *(float2*)P0 = make_float2(acc[mt][nt][0], acc[mt][nt][1]);
                *(float2*)P1 = make_float2(acc[mt][nt][2], acc[mt][nt][3]);
            } else {
                *(float2*)(C + (size_t)r0 * N + c) = make_float2(acc[mt][nt][0], acc[mt][nt][1]);
                *(float2*)(C + (size_t)(r0 + 8) * N + c) = make_float2(acc[mt][nt][2], acc[mt][nt][3]);
            }
        }
    }
}

// stage 1: three fused GEMMs [4096,1024] x [256,1024]^T  (plain tf32, 2 CTAs/SM)
__global__ void __launch_bounds__(256, 2) k_stage1(const float* __restrict__ x,
                                                   const float* __restrict__ w0,
                                                   const float* __restrict__ w1,
                                                   const float* __restrict__ w2,
                                                   float* __restrict__ c0,
                                                   float* __restrict__ c1,
                                                   float* __restrict__ c2) {
    int sub = blockIdx.x >> 1;
    const float* B = (sub == 0) ? w0 : (sub == 1) ? w1 : w2;
    float* C = (sub == 0) ? c0 : (sub == 1) ? c1 : c2;
    gemm_body<1024, 256, false, false>(x, B, C, blockIdx.y * 128, (blockIdx.x & 1) * 128);
}

// stage 2: five fused GEMMs [4096,256] x [1024,256]^T  (plain tf32; sub4 packs V)
__global__ void __launch_bounds__(256, 2) k_stage2(const float* __restrict__ qlat,
                                                   const float* __restrict__ krlat,
                                                   const float* __restrict__ kv,
                                                   const float* __restrict__ wqr,
                                                   const float* __restrict__ wqu,
                                                   const float* __restrict__ wku,
                                                   const float* __restrict__ wvu,
                                                   float* __restrict__ qr,
                                                   float* __restrict__ qn,
                                                   float* __restrict__ krf,
                                                   float* __restrict__ knf,
                                                   float* __restrict__ vpk) {
    int sub = blockIdx.x >> 3;
    const float* A = (sub <= 1) ? qlat : (sub == 2) ? krlat : kv;
    const float* B = (sub == 0) ? wqr : (sub == 1) ? wqu : (sub == 2) ? wku : (sub == 3) ? wku : wvu;
    if (sub == 4)
        gemm_body<256, 1024, false, true>(A, B, vpk, blockIdx.y * 128, (blockIdx.x & 7) * 128);
    else {
        float* C = (sub == 0) ? qr : (sub == 1) ? qn : (sub == 2) ? krf : knf;
        gemm_body<256, 1024, false, false>(A, B, C, blockIdx.y * 128, (blockIdx.x & 7) * 128);
    }
}

// output projection [4096,1024] x [1024,1024]^T  (plain tf32, 2 CTAs/SM)
__global__ void __launch_bounds__(256, 2) k_wo(const float* __restrict__ y,
                                               const float* __restrict__ wo,
                                               float* __restrict__ out) {
    gemm_body<1024, 1024, false, false>(y, wo, out, blockIdx.y * 128, blockIdx.x * 128);
}

// ---------------- RoPE table + pack ----------------
__global__ void __launch_bounds__(256) rope_fill(float* __restrict__ tab) {
    int i = blockIdx.x * 256 + threadIdx.x;
    int d2 = i & 31, s = i >> 5;
    float inv = (float)exp(-(double)d2 * (9.210340371976184 / 32.0));
    float ang = (float)s * inv;
    float c, sn;
    sincosf(ang, &sn, &c);
    tab[s * 64 + d2] = c;
    tab[s * 64 + 32 + d2] = sn;
}

// output pre-rounded to tf32 so flash can raw-copy K via cp.async
// (flash's own f2tf on load/stage is idempotent -> bit-identical results)
__global__ void __launch_bounds__(256) rope_pack(const float* __restrict__ rin,
                                                 const float* __restrict__ nin,
                                                 const float* __restrict__ tab,
                                                 float* __restrict__ out) {
    int idx = blockIdx.x * 256 + threadIdx.x;
    int d2 = idx & 31;
    int h = (idx >> 5) & 15;
    int tk = idx >> 9;
    int s = tk & (SEQ - 1);
    int b = tk >> 11;

    const float* rp = rin + (size_t)tk * EMB + h * 64;
    float x1 = rp[d2], x2 = rp[d2 + 32];
    float c = tab[s * 64 + d2];
    float sn = tab[s * 64 + 32 + d2];
    float* o = out + (((size_t)(b * NH + h)) * SEQ + s) * 128;
    o[d2] = f2tf(x1 * c - x2 * sn);
    o[d2 + 32] = f2tf(x2 * c + x1 * sn);
    const float* np = nin + (size_t)tk * EMB + h * 64;
    o[64 + d2] = f2tf(np[d2]);
    o[96 + d2] = f2tf(np[d2 + 32]);
}

// ---------------- flash attention (tf32 mma; Q in regs, cp.async 2-stage K) -------
#define FSQ 132
#define FSP 68
// layout: sK0 = smf+0 (64x132), sK1 = smf+8448, sVt = smf+16896 (64x68),
//         sP = smf+21248 (128x68). Q staging (128x132) overlays sK0|sK1 exactly.
#define FLASH_FLOATS (2 * 64 * FSQ + 64 * FSP + 128 * FSP)   // 29952 floats = 119808 B

__global__ void __launch_bounds__(256, 1) flash_mma(const float* __restrict__ Q,
                                                    const float* __restrict__ K,
                                                    const float* __restrict__ V,
                                                    float* __restrict__ Y) {
    extern __shared__ float smf[];
    float* sKst[2] = { smf, smf + 64 * FSQ };
    float* sVt = smf + 2 * 64 * FSQ;            // 64 x 68  ([vdim][key])
    float* sP  = sVt + 64 * FSP;                // 128 x 68

    const int tid = threadIdx.x, lane = tid & 31, w = tid >> 5;
    const int g = lane >> 2, t = lane & 3;
    const int bh = blockIdx.y;
    const int qb = gridDim.x - 1 - blockIdx.x;   // longest blocks first
    const int q0 = qb * 128;
    const int bb = bh >> 4, h = bh & 15;

    const float* Qb = Q + ((size_t)bh * SEQ + q0) * 128;
    const float* Kb = K + (size_t)bh * SEQ * 128;
    const float* Vb = V + (size_t)bh * SEQ * 64;

    // stage Q into the (overlaid) smem region, pull fragments into registers
    for (int i = tid; i < 128 * 32; i += 256) {
        int r = i >> 5, c = (i & 31) << 2;
        float4 v = *(const float4*)(Qb + (size_t)r * 128 + c);
        *(float4*)(smf + r * FSQ + c) =
            make_float4(f2tf(v.x), f2tf(v.y), f2tf(v.z), f2tf(v.w));
    }
    __syncthreads();

    uint32_t qa[16][4];
    {
        const float* qp = smf + (w * 16 + g) * FSQ + t;
#pragma unroll
        for (int k8 = 0; k8 < 16; k8++) {
            const float* p = qp + k8 * 8;
            qa[k8][0] = __float_as_uint(p[0]);
            qa[k8][1] = __float_as_uint(p[8 * FSQ]);
            qa[k8][2] = __float_as_uint(p[4]);
            qa[k8][3] = __float_as_uint(p[8 * FSQ + 4]);
        }
    }
    __syncthreads();   // Q staging dead; smem now owned by sK0/sK1/sVt/sP

    // per-thread cp.async chunk coordinates for K tiles (8 x 16B per thread)
    const int kr = tid >> 5;
    const int kc = (tid & 31) << 2;
    const uint32_t kdst0 = (uint32_t)__cvta_generic_to_shared(sKst[0]);
    const uint32_t kdst1 = (uint32_t)__cvta_generic_to_shared(sKst[1]);

    // issue K tile 0 -> sK0
    {
#pragma unroll
        for (int j = 0; j < 8; j++) {
            int r = kr + j * 8;
            asm volatile("cp.async.cg.shared.global [%0], [%1], 16;"
                         :: "r"(kdst0 + (r * FSQ + kc) * 4),
                            "l"(Kb + (size_t)r * 128 + kc));
        }
        asm volatile("cp.async.commit_group;");
    }

    // V prefetch registers (tile 0)
    int vr[4], vc[4];
#pragma unroll
    for (int i = 0; i < 4; i++) {
        int idx = tid + i * 256;
        vr[i] = idx >> 4;            // key row within tile
        vc[i] = (idx & 15) << 2;     // vdim col
    }
    float4 vp[4];
#pragma unroll
    for (int i = 0; i < 4; i++)
        vp[i] = *(const float4*)(Vb + (size_t)vr[i] * 64 + vc[i]);

    float o[8][4] = {};
    float m0r = -3.0e38f, m1r = -3.0e38f, l0 = 0.0f, l1 = 0.0f;
    const float scale = 0.08838834764831845f;   // 1/sqrt(128)
    const int row0 = q0 + w * 16 + g, row1 = row0 + 8;
    const int nkb = qb * 2 + 2;

    for (int kb = 0; kb < nkb; kb++) {
        const int k0 = kb * 64;
        const int cur = kb & 1;
        const bool pre = (kb + 1 < nkb);
        __syncthreads();   // all warps done reading sK[cur^1] (prev iter) and sVt/sP

        // issue cp.async for next K tile into the alternate stage
        if (pre) {
            const float* Kn = Kb + (size_t)(k0 + 64) * 128;
            const uint32_t dstb = cur ? kdst0 : kdst1;
#pragma unroll
            for (int j = 0; j < 8; j++) {
                int r = kr + j * 8;
                asm volatile("cp.async.cg.shared.global [%0], [%1], 16;"
                             :: "r"(dstb + (r * FSQ + kc) * 4),
                                "l"(Kn + (size_t)r * 128 + kc));
            }
            asm volatile("cp.async.commit_group;");
        }

        // store prefetched V tile (transposed)
#pragma unroll
        for (int i = 0; i < 4; i++) {
            float* d = sVt + vr[i];
            d[(vc[i] + 0) * FSP] = f2tf(vp[i].x);
            d[(vc[i] + 1) * FSP] = f2tf(vp[i].y);
            d[(vc[i] + 2) * FSP] = f2tf(vp[i].z);
            d[(vc[i] + 3) * FSP] = f2tf(vp[i].w);
        }

        // wait for current K tile (allow the just-issued one to stay in flight)
        if (pre) asm volatile("cp.async.wait_group 1;");
        else     asm volatile("cp.async.wait_group 0;");
        __syncthreads();

        // S = Q K^T  (warp: 16 x 64)
        float s[8][4] = {};
        const float* sK = sKst[cur];
#pragma unroll
        for (int k8 = 0; k8 < 16; k8++) {
            int kk = k8 * 8 + t;
#pragma unroll
            for (int nt = 0; nt < 8; nt++) {
                uint32_t b[2];
                const float* bp = sK + (nt * 8 + g) * FSQ + kk;
                b[0] = __float_as_uint(bp[0]);
                b[1] = __float_as_uint(bp[4]);
                mma8(s[nt], qa[k8], b);
            }
        }

        // prefetch next V tile into registers (latency hidden by softmax + PV)
        if (pre) {
            const float* Vn = Vb + (size_t)(k0 + 64) * 64;
#pragma unroll
            for (int i = 0; i < 4; i++)
                vp[i] = *(const float4*)(Vn + (size_t)vr[i] * 64 + vc[i]);
        }

        // mask + scale + row max
        float mx0 = -3.0e38f, mx1 = -3.0e38f;
#pragma unroll
        for (int nt = 0; nt < 8; nt++) {
            int c0 = k0 + nt * 8 + 2 * t;
            s[nt][0] = (c0 <= row0) ? s[nt][0] * scale : -3.0e38f;
            s[nt][1] = (c0 + 1 <= row0) ? s[nt][1] * scale : -3.0e38f;
            s[nt][2] = (c0 <= row1) ? s[nt][2] * scale : -3.0e38f;
            s[nt][3] = (c0 + 1 <= row1) ? s[nt][3] * scale : -3.0e38f;
            mx0 = fmaxf(mx0, fmaxf(s[nt][0], s[nt][1]));
            mx1 = fmaxf(mx1, fmaxf(s[nt][2], s[nt][3]));
        }
        mx0 = fmaxf(mx0, __shfl_xor_sync(0xffffffffu, mx0, 1));
        mx0 = fmaxf(mx0, __shfl_xor_sync(0xffffffffu, mx0, 2));
        mx1 = fmaxf(mx1, __shfl_xor_sync(0xffffffffu, mx1, 1));
        mx1 = fmaxf(mx1, __shfl_xor_sync(0xffffffffu, mx1, 2));
        float mn0 = fmaxf(m0r, mx0), mn1 = fmaxf(m1r, mx1);
        float a0 = __expf(m0r - mn0), a1 = __expf(m1r - mn1);
        m0r = mn0; m1r = mn1;

        float sum0 = 0.0f, sum1 = 0.0f;
        float* prow0 = sP + (w * 16 + g) * FSP;
        float* prow1 = prow0 + 8 * FSP;
#pragma unroll
        for (int nt = 0; nt < 8; nt++) {
            float p00 = f2tf(__expf(s[nt][0] - mn0));
            float p01 = f2tf(__expf(s[nt][1] - mn0));
            float p10 = f2tf(__expf(s[nt][2] - mn1));
            float p11 = f2tf(__expf(s[nt][3] - mn1));
            sum0 += p00 + p01;
            sum1 += p10 + p11;
            *(float2*)(prow0 + nt * 8 + 2 * t) = make_float2(p00, p01);
            *(float2*)(prow1 + nt * 8 + 2 * t) = make_float2(p10, p11);
        }
        sum0 += __shfl_xor_sync(0xffffffffu, sum0, 1);
        sum0 += __shfl_xor_sync(0xffffffffu, sum0, 2);
        sum1 += __shfl_xor_sync(0xffffffffu, sum1, 1);
        sum1 += __shfl_xor_sync(0xffffffffu, sum1, 2);
        l0 = l0 * a0 + sum0;
        l1 = l1 * a1 + sum1;
#pragma unroll
        for (int nt = 0; nt < 8; nt++) {
            o[nt][0] *= a0; o[nt][1] *= a0; o[nt][2] *= a1; o[nt][3] *= a1;
        }
        __syncwarp();

        // O += P V   (warp: 16 x 64, K=64)
#pragma unroll
        for (int k8 = 0; k8 < 8; k8++) {
            int kk = k8 * 8 + t;
            uint32_t a[4];
            const float* ap = sP + (w * 16 + g) * FSP + kk;
            a[0] = __float_as_uint(ap[0]);
            a[1] = __float_as_uint(ap[8 * FSP]);
            a[2] = __float_as_uint(ap[4]);
            a[3] = __float_as_uint(ap[8 * FSP + 4]);
#pragma unroll
            for (int nt = 0; nt < 8; nt++) {
                uint32_t b[2];
                const float* bp = sVt + (nt * 8 + g) * FSP + kk;
                b[0] = __float_as_uint(bp[0]);
                b[1] = __float_as_uint(bp[4]);
                mma8(o[nt], a, b);
            }
        }
    }

    float i0 = 1.0f / l0, i1 = 1.0f / l1;
    float* Y0 = Y + ((size_t)(bb * SEQ) + row0) * EMB + h * 64;
    float* Y1 = Y + ((size_t)(bb * SEQ) + row1) * EMB + h * 64;
#pragma unroll
    for (int nt = 0; nt < 8; nt++) {
        int c = nt * 8 + 2 * t;
        *(float2*)(Y0 + c) = make_float2(o[nt][0] * i0, o[nt][1] * i0);
        *(float2*)(Y1 + c) = make_float2(o[nt][2] * i1, o[nt][3] * i1);
    }
}

// ---------------- launcher ----------------
extern "C" void kernel_launch(void* const* d_in, const int* in_sizes, int n_in,
                              void* d_out, int out_size) {
    const float* x        = (const float*)d_in[0];
    const float* wq_down  = (const float*)d_in[1];
    const float* wk_rope  = (const float*)d_in[2];
    const float* wkv_down = (const float*)d_in[3];
    const float* wq_rope  = (const float*)d_in[4];
    const float* wq_up    = (const float*)d_in[5];
    const float* wk_up    = (const float*)d_in[6];
    const float* wv_up    = (const float*)d_in[7];
    const float* wo       = (const float*)d_in[8];
    float* out = (float*)d_out;

    float *qlat, *krlat, *kv, *qr, *qn, *krf, *knf, *q, *k, *v, *y, *tab;
    cudaGetSymbolAddress((void**)&qlat,  g_qlat);
    cudaGetSymbolAddress((void**)&krlat, g_krlat);
    cudaGetSymbolAddress((void**)&kv,    g_kv);
    cudaGetSymbolAddress((void**)&qr,    g_qr);
    cudaGetSymbolAddress((void**)&qn,    g_qn);
    cudaGetSymbolAddress((void**)&krf,   g_krf);
    cudaGetSymbolAddress((void**)&knf,   g_knf);
    cudaGetSymbolAddress((void**)&q,     g_q);
    cudaGetSymbolAddress((void**)&k,     g_k);
    cudaGetSymbolAddress((void**)&v,     g_v);
    cudaGetSymbolAddress((void**)&y,     g_y);
    cudaGetSymbolAddress((void**)&tab,   g_rope);

    const int smem_nosplit = 2 * 128 * GSTR * 4;   // 36864
    const int flash_smem = FLASH_FLOATS * 4;       // 119808
    cudaFuncSetAttribute(k_stage1, cudaFuncAttributeMaxDynamicSharedMemorySize, smem_nosplit);
    cudaFuncSetAttribute(k_stage2, cudaFuncAttributeMaxDynamicSharedMemorySize, smem_nosplit);
    cudaFuncSetAttribute(k_wo,     cudaFuncAttributeMaxDynamicSharedMemorySize, smem_nosplit);
    cudaFuncSetAttribute(flash_mma, cudaFuncAttributeMaxDynamicSharedMemorySize, flash_smem);

    // rope table
    rope_fill<<<(SEQ * 32) / 256, 256>>>(tab);

    // stage 1: latent projections (fused 3-way, plain tf32, 2 CTAs/SM)
    k_stage1<<<dim3(6, 32), 256, smem_nosplit>>>(x, wq_down, wk_rope, wkv_down, qlat, krlat, kv);

    // stage 2: up-projections (fused 5-way, plain tf32; V packed in epilogue)
    k_stage2<<<dim3(40, 32), 256, smem_nosplit>>>(qlat, krlat, kv,
                                                  wq_rope, wq_up, wk_up, wv_up,
                                                  qr, qn, krf, knf, v);

    // stage 3: rope + pack Q and K (outputs pre-rounded to tf32)
    rope_pack<<<(TOKENS * NH * 32) / 256, 256>>>(qr, qn, tab, q);
    rope_pack<<<(TOKENS * NH * 32) / 256, 256>>>(krf, knf, tab, k);

    // stage 4: causal flash attention (cp.async double-buffered K)
    flash_mma<<<dim3(SEQ / 128, NBH), 256, flash_smem>>>(q, k, v, y);

    // stage 5: output projection
    k_wo<<<dim3(8, 32), 256, smem_nosplit>>>(y, wo, out);
}

// round 16
// speedup vs baseline: 1.3208x; 1.3208x over previous
#include <cuda_runtime.h>
#include <math.h>
#include <stdint.h>

#define TOKENS 4096
#define SEQ    2048
#define EMB    1024
#define RANK   256
#define NH     16
#define NBH    32

// ---------------- scratch ----------------
__device__ float g_qlat [TOKENS * RANK];
__device__ float g_krlat[TOKENS * RANK];
__device__ float g_kv   [TOKENS * RANK];
__device__ float g_qr   [TOKENS * EMB];
__device__ float g_qn   [TOKENS * EMB];
__device__ float g_krf  [TOKENS * EMB];
__device__ float g_knf  [TOKENS * EMB];
__device__ float g_q    [(size_t)NBH * SEQ * 128];
__device__ float g_k    [(size_t)NBH * SEQ * 128];
__device__ float g_v    [(size_t)NBH * SEQ * 64];
__device__ float g_y    [TOKENS * EMB];
__device__ float g_rope [SEQ * 64];   // [s][0..31]=cos, [s][32..63]=sin

// ---------------- helpers ----------------
__device__ __forceinline__ uint32_t f2t(float x) {
    uint32_t r;
    asm("cvt.rna.tf32.f32 %0, %1;" : "=r"(r) : "f"(x));
    return r;
}
__device__ __forceinline__ float f2tf(float x) { return __uint_as_float(f2t(x)); }

__device__ __forceinline__ void mma8(float* d, const uint32_t* a, const uint32_t* b) {
    asm volatile(
        "mma.sync.aligned.m16n8k8.row.col.f32.tf32.tf32.f32 "
        "{%0,%1,%2,%3}, {%4,%5,%6,%7}, {%8,%9}, {%0,%1,%2,%3};"
        : "+f"(d[0]), "+f"(d[1]), "+f"(d[2]), "+f"(d[3])
        : "r"(a[0]), "r"(a[1]), "r"(a[2]), "r"(a[3]), "r"(b[0]), "r"(b[1]));
}

// ---------------- tf32 GEMM body: C = A(128 rows) * B(128 rows)^T ----------------
// BM=128, BN=128, BK=32, 256 threads (8 warps: 2M x 4N, warp tile 64x32).
// SPLIT: 3-pass hi/lo error compensation. PACKV: epilogue writes [bh][s][64] layout.
#define GSTR 36

template <int K, int N, bool SPLIT, bool PACKV>
__device__ __forceinline__ void gemm_body(const float* __restrict__ A,
                                          const float* __restrict__ B,
                                          float* __restrict__ C,
                                          int row0, int col0) {
    extern __shared__ float smg[];
    float* sAh = smg;
    float* sBh = sAh + 128 * GSTR;
    float* sAl = sBh + 128 * GSTR;           // only used if SPLIT
    float* sBl = sAl + 128 * GSTR;

    const int tid = threadIdx.x, lane = tid & 31, warp = tid >> 5;
    const int g = lane >> 2, t = lane & 3;
    const int wm = warp >> 2, wn = warp & 3;

    const float* Ab = A + (size_t)row0 * K;
    const float* Bb = B + (size_t)col0 * K;

    int rr[4], cc[4];
#pragma unroll
    for (int i = 0; i < 4; i++) { int idx = tid + i * 256; rr[i] = idx >> 3; cc[i] = (idx & 7) << 2; }

    float4 pa[4], pb[4];
#pragma unroll
    for (int i = 0; i < 4; i++) {
        pa[i] = *(const float4*)(Ab + (size_t)rr[i] * K + cc[i]);
        pb[i] = *(const float4*)(Bb + (size_t)rr[i] * K + cc[i]);
    }

    float acc[4][4][4] = {};

#pragma unroll 1
    for (int k0 = 0; k0 < K; k0 += 32) {
        __syncthreads();
#pragma unroll
        for (int i = 0; i < 4; i++) {
            float4 v = pa[i];
            float hx = f2tf(v.x), hy = f2tf(v.y), hz = f2tf(v.z), hw = f2tf(v.w);
            *(float4*)(sAh + rr[i] * GSTR + cc[i]) = make_float4(hx, hy, hz, hw);
            if (SPLIT)
                *(float4*)(sAl + rr[i] * GSTR + cc[i]) =
                    make_float4(f2tf(v.x - hx), f2tf(v.y - hy), f2tf(v.z - hz), f2tf(v.w - hw));
            v = pb[i];
            hx = f2tf(v.x); hy = f2tf(v.y); hz = f2tf(v.z); hw = f2tf(v.w);
            *(float4*)(sBh + rr[i] * GSTR + cc[i]) = make_float4(hx, hy, hz, hw);
            if (SPLIT)
                *(float4*)(sBl + rr[i] * GSTR + cc[i]) =
                    make_float4(f2tf(v.x - hx), f2tf(v.y - hy), f2tf(v.z - hz), f2tf(v.w - hw));
        }
        __syncthreads();
        if (k0 + 32 < K) {
#pragma unroll
            for (int i = 0; i < 4; i++) {
                pa[i] = *(const float4*)(Ab + (size_t)rr[i] * K + k0 + 32 + cc[i]);
                pb[i] = *(const float4*)(Bb + (size_t)rr[i] * K + k0 + 32 + cc[i]);
            }
        }
#pragma unroll
        for (int k8 = 0; k8 < 4; k8++) {
            const int kb = k8 * 8 + t;
            uint32_t ah[4][4], al[4][4], bh[4][2], bl[4][2];
#pragma unroll
            for (int mt = 0; mt < 4; mt++) {
                const float* p = sAh + (wm * 64 + mt * 16 + g) * GSTR + kb;
                ah[mt][0] = __float_as_uint(p[0]);
                ah[mt][1] = __float_as_uint(p[8 * GSTR]);
                ah[mt][2] = __float_as_uint(p[4]);
                ah[mt][3] = __float_as_uint(p[8 * GSTR + 4]);
                if (SPLIT) {
                    const float* q = sAl + (wm * 64 + mt * 16 + g) * GSTR + kb;
                    al[mt][0] = __float_as_uint(q[0]);
                    al[mt][1] = __float_as_uint(q[8 * GSTR]);
                    al[mt][2] = __float_as_uint(q[4]);
                    al[mt][3] = __float_as_uint(q[8 * GSTR + 4]);
                }
            }
#pragma unroll
            for (int nt = 0; nt < 4; nt++) {
                const float* p = sBh + (wn * 32 + nt * 8 + g) * GSTR + kb;
                bh[nt][0] = __float_as_uint(p[0]);
                bh[nt][1] = __float_as_uint(p[4]);
                if (SPLIT) {
                    const float* q = sBl + (wn * 32 + nt * 8 + g) * GSTR + kb;
                    bl[nt][0] = __float_as_uint(q[0]);
                    bl[nt][1] = __float_as_uint(q[4]);
                }
            }
#pragma unroll
            for (int mt = 0; mt < 4; mt++)
#pragma unroll
                for (int nt = 0; nt < 4; nt++) {
                    mma8(acc[mt][nt], ah[mt], bh[nt]);
                    if (SPLIT) {
                        mma8(acc[mt][nt], ah[mt], bl[nt]);
                        mma8(acc[mt][nt], al[mt], bh[nt]);
                    }
                }
        }
    }

#pragma unroll
    for (int mt = 0; mt < 4; mt++) {
        int r0 = row0 + wm * 64 + mt * 16 + g;
#pragma unroll
        for (int nt = 0; nt < 4; nt++) {
            int c = col0 + wn * 32 + nt * 8 + 2 * t;
            if (PACKV) {
                // pack [token][E] -> [b*16+h][s][64]
                int b0 = r0 >> 11, s0 = r0 & (SEQ - 1);
                int h = c >> 6, d = c & 63;
                float* P0 = C + (((size_t)(b0 * NH + h)) * SEQ + s0) * 64 + d;
                float* P1 = C + (((size_t)(b0 * NH + h)) * SEQ + s0 + 8) * 64 + d;
                *(float2*)P0 = make_float2(acc[mt][nt][0], acc[mt][nt][1]);
                *(float2*)P1 = make_float2(acc[mt][nt][2], acc[mt][nt][3]);
            } else {
                *(float2*)(C + (size_t)r0 * N + c) = make_float2(acc[mt][nt][0], acc[mt][nt][1]);
                *(float2*)(C + (size_t)(r0 + 8) * N + c) = make_float2(acc[mt][nt][2], acc[mt][nt][3]);
            }
        }
    }
}

// stage 1: three fused GEMMs [4096,1024] x [256,1024]^T  (split: high accuracy)
__global__ void __launch_bounds__(256, 1) k_stage1(const float* __restrict__ x,
                                                   const float* __restrict__ w0,
                                                   const float* __restrict__ w1,
                                                   const float* __restrict__ w2,
                                                   float* __restrict__ c0,
                                                   float* __restrict__ c1,
                                                   float* __restrict__ c2) {
    int sub = blockIdx.x >> 1;
    const float* B = (sub == 0) ? w0 : (sub == 1) ? w1 : w2;
    float* C = (sub == 0) ? c0 : (sub == 1) ? c1 : c2;
    gemm_body<1024, 256, true, false>(x, B, C, blockIdx.y * 128, (blockIdx.x & 1) * 128);
}

// stage 2: five fused GEMMs [4096,256] x [1024,256]^T  (plain tf32; sub4 packs V)
__global__ void __launch_bounds__(256, 2) k_stage2(const float* __restrict__ qlat,
                                                   const float* __restrict__ krlat,
                                                   const float* __restrict__ kv,
                                                   const float* __restrict__ wqr,
                                                   const float* __restrict__ wqu,
                                                   const float* __restrict__ wku,
                                                   const float* __restrict__ wvu,
                                                   float* __restrict__ qr,
                                                   float* __restrict__ qn,
                                                   float* __restrict__ krf,
                                                   float* __restrict__ knf,
                                                   float* __restrict__ vpk) {
    int sub = blockIdx.x >> 3;
    const float* A = (sub <= 1) ? qlat : (sub == 2) ? krlat : kv;
    const float* B = (sub == 0) ? wqr : (sub == 1) ? wqu : (sub == 2) ? wku : (sub == 3) ? wku : wvu;
    if (sub == 4)
        gemm_body<256, 1024, false, true>(A, B, vpk, blockIdx.y * 128, (blockIdx.x & 7) * 128);
    else {
        float* C = (sub == 0) ? qr : (sub == 1) ? qn : (sub == 2) ? krf : knf;
        gemm_body<256, 1024, false, false>(A, B, C, blockIdx.y * 128, (blockIdx.x & 7) * 128);
    }
}

// output projection [4096,1024] x [1024,1024]^T  (plain tf32, 2 CTAs/SM)
__global__ void __launch_bounds__(256, 2) k_wo(const float* __restrict__ y,
                                               const float* __restrict__ wo,
                                               float* __restrict__ out) {
    gemm_body<1024, 1024, false, false>(y, wo, out, blockIdx.y * 128, blockIdx.x * 128);
}

// ---------------- RoPE table + pack ----------------
__global__ void __launch_bounds__(256) rope_fill(float* __restrict__ tab) {
    int i = blockIdx.x * 256 + threadIdx.x;
    int d2 = i & 31, s = i >> 5;
    float inv = (float)exp(-(double)d2 * (9.210340371976184 / 32.0));
    float ang = (float)s * inv;
    float c, sn;
    sincosf(ang, &sn, &c);
    tab[s * 64 + d2] = c;
    tab[s * 64 + 32 + d2] = sn;
}

// fused Q+K rope-pack: first half of grid does Q (qr,qn -> q), second half K
// (krf,knf -> k). Outputs pre-rounded to tf32 so flash can raw-copy via cp.async.
__global__ void __launch_bounds__(256) rope_pack2(const float* __restrict__ qr,
                                                  const float* __restrict__ qn,
                                                  const float* __restrict__ krf,
                                                  const float* __restrict__ knf,
                                                  const float* __restrict__ tab,
                                                  float* __restrict__ qo,
                                                  float* __restrict__ ko) {
    const int HALF = (TOKENS * NH * 32) / 256;   // 8192 blocks per half
    int blk = blockIdx.x;
    const float* rin;
    const float* nin;
    float* out;
    if (blk < HALF) { rin = qr; nin = qn; out = qo; }
    else            { rin = krf; nin = knf; out = ko; blk -= HALF; }

    int idx = blk * 256 + threadIdx.x;
    int d2 = idx & 31;
    int h = (idx >> 5) & 15;
    int tk = idx >> 9;
    int s = tk & (SEQ - 1);
    int b = tk >> 11;

    const float* rp = rin + (size_t)tk * EMB + h * 64;
    float x1 = rp[d2], x2 = rp[d2 + 32];
    float c = tab[s * 64 + d2];
    float sn = tab[s * 64 + 32 + d2];
    float* o = out + (((size_t)(b * NH + h)) * SEQ + s) * 128;
    o[d2] = f2tf(x1 * c - x2 * sn);
    o[d2 + 32] = f2tf(x2 * c + x1 * sn);
    const float* np = nin + (size_t)tk * EMB + h * 64;
    o[64 + d2] = f2tf(np[d2]);
    o[96 + d2] = f2tf(np[d2 + 32]);
}

// ---------------- flash attention (tf32 mma; Q in regs, cp.async 2-stage K) -------
#define FSQ 132
#define FSP 68
// layout: sK0 = smf+0 (64x132), sK1 = smf+8448, sVt = smf+16896 (64x68),
//         sP = smf+21248 (128x68). Q staging (128x132) overlays sK0|sK1 exactly.
#define FLASH_FLOATS (2 * 64 * FSQ + 64 * FSP + 128 * FSP)   // 29952 floats = 119808 B

__global__ void __launch_bounds__(256, 1) flash_mma(const float* __restrict__ Q,
                                                    const float* __restrict__ K,
                                                    const float* __restrict__ V,
                                                    float* __restrict__ Y) {
    extern __shared__ float smf[];
    float* sKst[2] = { smf, smf + 64 * FSQ };
    float* sVt = smf + 2 * 64 * FSQ;            // 64 x 68  ([vdim][key])
    float* sP  = sVt + 64 * FSP;                // 128 x 68

    const int tid = threadIdx.x, lane = tid & 31, w = tid >> 5;
    const int g = lane >> 2, t = lane & 3;
    const int bh = blockIdx.y;
    const int qb = gridDim.x - 1 - blockIdx.x;   // longest blocks first
    const int q0 = qb * 128;
    const int bb = bh >> 4, h = bh & 15;

    const float* Qb = Q + ((size_t)bh * SEQ + q0) * 128;
    const float* Kb = K + (size_t)bh * SEQ * 128;
    const float* Vb = V + (size_t)bh * SEQ * 64;

    // stage Q into the (overlaid) smem region, pull fragments into registers
    for (int i = tid; i < 128 * 32; i += 256) {
        int r = i >> 5, c = (i & 31) << 2;
        float4 v = *(const float4*)(Qb + (size_t)r * 128 + c);
        *(float4*)(smf + r * FSQ + c) =
            make_float4(f2tf(v.x), f2tf(v.y), f2tf(v.z), f2tf(v.w));
    }
    __syncthreads();

    uint32_t qa[16][4];
    {
        const float* qp = smf + (w * 16 + g) * FSQ + t;
#pragma unroll
        for (int k8 = 0; k8 < 16; k8++) {
            const float* p = qp + k8 * 8;
            qa[k8][0] = __float_as_uint(p[0]);
            qa[k8][1] = __float_as_uint(p[8 * FSQ]);
            qa[k8][2] = __float_as_uint(p[4]);
            qa[k8][3] = __float_as_uint(p[8 * FSQ + 4]);
        }
    }
    __syncthreads();   // Q staging dead; smem now owned by sK0/sK1/sVt/sP

    // per-thread cp.async chunk coordinates for K tiles (8 x 16B per thread)
    const int kr = tid >> 5;
    const int kc = (tid & 31) << 2;
    const uint32_t kdst0 = (uint32_t)__cvta_generic_to_shared(sKst[0]);
    const uint32_t kdst1 = (uint32_t)__cvta_generic_to_shared(sKst[1]);

    // issue K tile 0 -> sK0
    {
#pragma unroll
        for (int j = 0; j < 8; j++) {
            int r = kr + j * 8;
            asm volatile("cp.async.cg.shared.global [%0], [%1], 16;"
                         :: "r"(kdst0 + (r * FSQ + kc) * 4),
                            "l"(Kb + (size_t)r * 128 + kc));
        }
        asm volatile("cp.async.commit_group;");
    }

    // V prefetch registers (tile 0)
    int vr[4], vc[4];
#pragma unroll
    for (int i = 0; i < 4; i++) {
        int idx = tid + i * 256;
        vr[i] = idx >> 4;            // key row within tile
        vc[i] = (idx & 15) << 2;     // vdim col
    }
    float4 vp[4];
#pragma unroll
    for (int i = 0; i < 4; i++)
        vp[i] = *(const float4*)(Vb + (size_t)vr[i] * 64 + vc[i]);

    float o[8][4] = {};
    float m0r = -3.0e38f, m1r = -3.0e38f, l0 = 0.0f, l1 = 0.0f;
    const float scale = 0.08838834764831845f;   // 1/sqrt(128)
    const int row0 = q0 + w * 16 + g, row1 = row0 + 8;
    const int nkb = qb * 2 + 2;

    for (int kb = 0; kb < nkb; kb++) {
        const int k0 = kb * 64;
        const int cur = kb & 1;
        const bool pre = (kb + 1 < nkb);
        __syncthreads();   // all warps done reading sK[cur^1] (prev iter) and sVt/sP

        // issue cp.async for next K tile into the alternate stage
        if (pre) {
            const float* Kn = Kb + (size_t)(k0 + 64) * 128;
            const uint32_t dstb = cur ? kdst0 : kdst1;
#pragma unroll
            for (int j = 0; j < 8; j++) {
                int r = kr + j * 8;
                asm volatile("cp.async.cg.shared.global [%0], [%1], 16;"
                             :: "r"(dstb + (r * FSQ + kc) * 4),
                                "l"(Kn + (size_t)r * 128 + kc));
            }
            asm volatile("cp.async.commit_group;");
        }

        // store prefetched V tile (transposed)
#pragma unroll
        for (int i = 0; i < 4; i++) {
            float* d = sVt + vr[i];
            d[(vc[i] + 0) * FSP] = f2tf(vp[i].x);
            d[(vc[i] + 1) * FSP] = f2tf(vp[i].y);
            d[(vc[i] + 2) * FSP] = f2tf(vp[i].z);
            d[(vc[i] + 3) * FSP] = f2tf(vp[i].w);
        }

        // wait for current K tile (allow the just-issued one to stay in flight)
        if (pre) asm volatile("cp.async.wait_group 1;");
        else     asm volatile("cp.async.wait_group 0;");
        __syncthreads();

        // S = Q K^T  (warp: 16 x 64)
        float s[8][4] = {};
        const float* sK = sKst[cur];
#pragma unroll
        for (int k8 = 0; k8 < 16; k8++) {
            int kk = k8 * 8 + t;
#pragma unroll
            for (int nt = 0; nt < 8; nt++) {
                uint32_t b[2];
                const float* bp = sK + (nt * 8 + g) * FSQ + kk;
                b[0] = __float_as_uint(bp[0]);
                b[1] = __float_as_uint(bp[4]);
                mma8(s[nt], qa[k8], b);
            }
        }

        // prefetch next V tile into registers (latency hidden by softmax + PV)
        if (pre) {
            const float* Vn = Vb + (size_t)(k0 + 64) * 64;
#pragma unroll
            for (int i = 0; i < 4; i++)
                vp[i] = *(const float4*)(Vn + (size_t)vr[i] * 64 + vc[i]);
        }

        // mask + scale + row max
        float mx0 = -3.0e38f, mx1 = -3.0e38f;
#pragma unroll
        for (int nt = 0; nt < 8; nt++) {
            int c0 = k0 + nt * 8 + 2 * t;
            s[nt][0] = (c0 <= row0) ? s[nt][0] * scale : -3.0e38f;
            s[nt][1] = (c0 + 1 <= row0) ? s[nt][1] * scale : -3.0e38f;
            s[nt][2] = (c0 <= row1) ? s[nt][2] * scale : -3.0e38f;
            s[nt][3] = (c0 + 1 <= row1) ? s[nt][3] * scale : -3.0e38f;
            mx0 = fmaxf(mx0, fmaxf(s[nt][0], s[nt][1]));
            mx1 = fmaxf(mx1, fmaxf(s[nt][2], s[nt][3]));
        }
        mx0 = fmaxf(mx0, __shfl_xor_sync(0xffffffffu, mx0, 1));
        mx0 = fmaxf(mx0, __shfl_xor_sync(0xffffffffu, mx0, 2));
        mx1 = fmaxf(mx1, __shfl_xor_sync(0xffffffffu, mx1, 1));
        mx1 = fmaxf(mx1, __shfl_xor_sync(0xffffffffu, mx1, 2));
        float mn0 = fmaxf(m0r, mx0), mn1 = fmaxf(m1r, mx1);
        float a0 = __expf(m0r - mn0), a1 = __expf(m1r - mn1);
        m0r = mn0; m1r = mn1;

        float sum0 = 0.0f, sum1 = 0.0f;
        float* prow0 = sP + (w * 16 + g) * FSP;
        float* prow1 = prow0 + 8 * FSP;
#pragma unroll
        for (int nt = 0; nt < 8; nt++) {
            float p00 = f2tf(__expf(s[nt][0] - mn0));
            float p01 = f2tf(__expf(s[nt][1] - mn0));
            float p10 = f2tf(__expf(s[nt][2] - mn1));
            float p11 = f2tf(__expf(s[nt][3] - mn1));
            sum0 += p00 + p01;
            sum1 += p10 + p11;
            *(float2*)(prow0 + nt * 8 + 2 * t) = make_float2(p00, p01);
            *(float2*)(prow1 + nt * 8 + 2 * t) = make_float2(p10, p11);
        }
        sum0 += __shfl_xor_sync(0xffffffffu, sum0, 1);
        sum0 += __shfl_xor_sync(0xffffffffu, sum0, 2);
        sum1 += __shfl_xor_sync(0xffffffffu, sum1, 1);
        sum1 += __shfl_xor_sync(0xffffffffu, sum1, 2);
        l0 = l0 * a0 + sum0;
        l1 = l1 * a1 + sum1;
#pragma unroll
        for (int nt = 0; nt < 8; nt++) {
            o[nt][0] *= a0; o[nt][1] *= a0; o[nt][2] *= a1; o[nt][3] *= a1;
        }
        __syncwarp();

        // O += P V   (warp: 16 x 64, K=64)
#pragma unroll
        for (int k8 = 0; k8 < 8; k8++) {
            int kk = k8 * 8 + t;
            uint32_t a[4];
            const float* ap = sP + (w * 16 + g) * FSP + kk;
            a[0] = __float_as_uint(ap[0]);
            a[1] = __float_as_uint(ap[8 * FSP]);
            a[2] = __float_as_uint(ap[4]);
            a[3] = __float_as_uint(ap[8 * FSP + 4]);
#pragma unroll
            for (int nt = 0; nt < 8; nt++) {
                uint32_t b[2];
                const float* bp = sVt + (nt * 8 + g) * FSP + kk;
                b[0] = __float_as_uint(bp[0]);
                b[1] = __float_as_uint(bp[4]);
                mma8(o[nt], a, b);
            }
        }
    }

    float i0 = 1.0f / l0, i1 = 1.0f / l1;
    float* Y0 = Y + ((size_t)(bb * SEQ) + row0) * EMB + h * 64;
    float* Y1 = Y + ((size_t)(bb * SEQ) + row1) * EMB + h * 64;
#pragma unroll
    for (int nt = 0; nt < 8; nt++) {
        int c = nt * 8 + 2 * t;
        *(float2*)(Y0 + c) = make_float2(o[nt][0] * i0, o[nt][1] * i0);
        *(float2*)(Y1 + c) = make_float2(o[nt][2] * i1, o[nt][3] * i1);
    }
}

// ---------------- launcher ----------------
extern "C" void kernel_launch(void* const* d_in, const int* in_sizes, int n_in,
                              void* d_out, int out_size) {
    const float* x        = (const float*)d_in[0];
    const float* wq_down  = (const float*)d_in[1];
    const float* wk_rope  = (const float*)d_in[2];
    const float* wkv_down = (const float*)d_in[3];
    const float* wq_rope  = (const float*)d_in[4];
    const float* wq_up    = (const float*)d_in[5];
    const float* wk_up    = (const float*)d_in[6];
    const float* wv_up    = (const float*)d_in[7];
    const float* wo       = (const float*)d_in[8];
    float* out = (float*)d_out;

    float *qlat, *krlat, *kv, *qr, *qn, *krf, *knf, *q, *k, *v, *y, *tab;
    cudaGetSymbolAddress((void**)&qlat,  g_qlat);
    cudaGetSymbolAddress((void**)&krlat, g_krlat);
    cudaGetSymbolAddress((void**)&kv,    g_kv);
    cudaGetSymbolAddress((void**)&qr,    g_qr);
    cudaGetSymbolAddress((void**)&qn,    g_qn);
    cudaGetSymbolAddress((void**)&krf,   g_krf);
    cudaGetSymbolAddress((void**)&knf,   g_knf);
    cudaGetSymbolAddress((void**)&q,     g_q);
    cudaGetSymbolAddress((void**)&k,     g_k);
    cudaGetSymbolAddress((void**)&v,     g_v);
    cudaGetSymbolAddress((void**)&y,     g_y);
    cudaGetSymbolAddress((void**)&tab,   g_rope);

    const int smem_split   = 4 * 128 * GSTR * 4;   // 73728
    const int smem_nosplit = 2 * 128 * GSTR * 4;   // 36864
    const int flash_smem = FLASH_FLOATS * 4;       // 119808
    cudaFuncSetAttribute(k_stage1, cudaFuncAttributeMaxDynamicSharedMemorySize, smem_split);
    cudaFuncSetAttribute(k_stage2, cudaFuncAttributeMaxDynamicSharedMemorySize, smem_nosplit);
    cudaFuncSetAttribute(k_wo,     cudaFuncAttributeMaxDynamicSharedMemorySize, smem_nosplit);
    cudaFuncSetAttribute(flash_mma, cudaFuncAttributeMaxDynamicSharedMemorySize, flash_smem);

    // rope table
    rope_fill<<<(SEQ * 32) / 256, 256>>>(tab);

    // stage 1: latent projections (fused 3-way, hi/lo split)
    k_stage1<<<dim3(6, 32), 256, smem_split>>>(x, wq_down, wk_rope, wkv_down, qlat, krlat, kv);

    // stage 2: up-projections (fused 5-way, plain tf32; V packed in epilogue)
    k_stage2<<<dim3(40, 32), 256, smem_nosplit>>>(qlat, krlat, kv,
                                                  wq_rope, wq_up, wk_up, wv_up,
                                                  qr, qn, krf, knf, v);

    // stage 3: fused Q+K rope-pack (one launch)
    rope_pack2<<<2 * (TOKENS * NH * 32) / 256, 256>>>(qr, qn, krf, knf, tab, q, k);

    // stage 4: causal flash attention (cp.async double-buffered K)
    flash_mma<<<dim3(SEQ / 128, NBH), 256, flash_smem>>>(q, k, v, y);

    // stage 5: output projection
    k_wo<<<dim3(8, 32), 256, smem_nosplit>>>(y, wo, out);
}